// round 5
// baseline (speedup 1.0000x reference)
#include <cuda_runtime.h>
#include <cuda_fp16.h>
#include <cstdint>
#include <cstddef>

// ---------------- problem constants ----------------
#define SEQA   4096
#define BATCH  8
#define DM     1024
#define MROWS  (SEQA*BATCH)          // 32768
#define NELEM_ACT ((size_t)MROWS*DM) // 33554432
#define NELEM_W   ((size_t)DM*DM)    // 1048576

static __device__ __forceinline__ float inv_alpha() { return 1.0f/1.5f; }
#define SCORE_SCALE 0.125f           // 1/sqrt(64)

// ---------------- scratch (device globals; allocation-free) ----------------
__device__ __half g_ahi[3][MROWS*DM];
__device__ __half g_alo[3][MROWS*DM];
__device__ __half g_wh[4][DM*DM];
__device__ float g_q[MROWS*DM];
__device__ float g_k[MROWS*DM];
__device__ float g_v[MROWS*DM];
__device__ __half g_x2hi[MROWS*DM];
__device__ __half g_x2lo[MROWS*DM];

// ---------------- PTX helpers (baseline ISA only: sm_80-era) ----------------
__device__ __forceinline__ uint32_t smem_u32(const void* p) {
    uint32_t r;
    asm("{ .reg .u64 t; cvta.to.shared.u64 t, %1; cvt.u32.u64 %0, t; }"
        : "=r"(r) : "l"(p));
    return r;
}
__device__ __forceinline__ void cpasync16(uint32_t saddr, const void* g) {
    asm volatile("cp.async.cg.shared.global [%0], [%1], 16;"
                 :: "r"(saddr), "l"(g) : "memory");
}
__device__ __forceinline__ void cp_commit() {
    asm volatile("cp.async.commit_group;" ::: "memory");
}
template<int N> __device__ __forceinline__ void cp_wait() {
    asm volatile("cp.async.wait_group %0;" :: "n"(N) : "memory");
}
__device__ __forceinline__ void ldsm4(uint32_t* r, uint32_t addr) {
    asm volatile("ldmatrix.sync.aligned.m8n8.x4.shared.b16 {%0,%1,%2,%3}, [%4];"
                 : "=r"(r[0]), "=r"(r[1]), "=r"(r[2]), "=r"(r[3]) : "r"(addr));
}
__device__ __forceinline__ void mma16816(float* d, const uint32_t* a, const uint32_t* b) {
    asm volatile(
        "mma.sync.aligned.m16n8k16.row.col.f32.f16.f16.f32 "
        "{%0,%1,%2,%3}, {%4,%5,%6,%7}, {%8,%9}, {%0,%1,%2,%3};"
        : "+f"(d[0]), "+f"(d[1]), "+f"(d[2]), "+f"(d[3])
        : "r"(a[0]), "r"(a[1]), "r"(a[2]), "r"(a[3]), "r"(b[0]), "r"(b[1]));
}

// ---------------- split kernels: fp32 -> fp16 (hi[,lo]) ----------------
__global__ void __launch_bounds__(256) split_fp16_kernel(
    const float4* __restrict__ x, uint4* __restrict__ hi, uint4* __restrict__ lo, int n8)
{
    int i = blockIdx.x * blockDim.x + threadIdx.x;
    if (i >= n8) return;
    float4 a = x[2*i];
    float4 b = x[2*i+1];
    float v[8] = {a.x, a.y, a.z, a.w, b.x, b.y, b.z, b.w};
    uint32_t hw[4], lw[4];
#pragma unroll
    for (int j = 0; j < 4; j++) {
        __half2 hp = __floats2half2_rn(v[2*j], v[2*j+1]);
        float l0 = v[2*j]   - __low2float(hp);
        float l1 = v[2*j+1] - __high2float(hp);
        __half2 lp = __floats2half2_rn(l0, l1);
        hw[j] = *reinterpret_cast<uint32_t*>(&hp);
        lw[j] = *reinterpret_cast<uint32_t*>(&lp);
    }
    hi[i] = make_uint4(hw[0], hw[1], hw[2], hw[3]);
    lo[i] = make_uint4(lw[0], lw[1], lw[2], lw[3]);
}

__global__ void __launch_bounds__(256) conv_fp16_kernel(
    const float4* __restrict__ x, uint4* __restrict__ h, int n8)
{
    int i = blockIdx.x * blockDim.x + threadIdx.x;
    if (i >= n8) return;
    float4 a = x[2*i];
    float4 b = x[2*i+1];
    float v[8] = {a.x, a.y, a.z, a.w, b.x, b.y, b.z, b.w};
    uint32_t hw[4];
#pragma unroll
    for (int j = 0; j < 4; j++) {
        __half2 hp = __floats2half2_rn(v[2*j], v[2*j+1]);
        hw[j] = *reinterpret_cast<uint32_t*>(&hp);
    }
    h[i] = make_uint4(hw[0], hw[1], hw[2], hw[3]);
}

// ---------------- HMMA split-fp16 GEMM ----------------
// C[32768,1024] = (Ahi+Alo) @ Bh^T + bias. Effective K = 2*1024 via 2 segments.
// CTA tile 128x128, K-chunk 64 fp16 (128B/row), 3-stage cp.async pipeline.
// 8 warps = 2(m) x 4(n); warp tile 64x32; mma.m16n8k16 grid 4x4 per k16 step.
#define BM 128
#define BN 128
#define BK 64
#define STAGES 3
#define STAGE_BYTES 16384                      // per operand per stage
#define GEMM_SMEM (STAGES * 2 * STAGE_BYTES)   // 98304
#define NCH 32                                 // 2 segs * 16 chunks

__global__ void __launch_bounds__(256, 2) gemm_hmma(
    const __half* __restrict__ Ahi, const __half* __restrict__ Alo,
    const __half* __restrict__ Bh,
    const float* __restrict__ bias, float* __restrict__ C)
{
    extern __shared__ __align__(1024) char smem[];
    const uint32_t sb = smem_u32(smem);
    const int tid  = threadIdx.x;
    const int lane = tid & 31;
    const int wid  = tid >> 5;
    const int wm   = wid >> 2;       // 0..1
    const int wn   = wid & 3;        // 0..3
    const int row0 = blockIdx.y * BM;
    const int col0 = blockIdx.x * BN;

    const int lr = tid >> 3;         // 0..31
    const int lc = tid & 7;          // 0..7 (16B columns)

    float acc[4][4][4];
#pragma unroll
    for (int a = 0; a < 4; a++)
#pragma unroll
        for (int b = 0; b < 4; b++)
#pragma unroll
            for (int c = 0; c < 4; c++) acc[a][b][c] = 0.0f;

    // ---- stage loader ----
    auto load_stage = [&](int s, int ch) {
        const __half* As = (ch < 16) ? Ahi : Alo;
        const int ksub = (ch & 15) * BK;
        const uint32_t sa = sb + (uint32_t)s * 2 * STAGE_BYTES;
        const uint32_t sbB = sa + STAGE_BYTES;
#pragma unroll
        for (int rep = 0; rep < 4; rep++) {
            int r = lr + rep * 32;
            uint32_t sw = (uint32_t)(r * 128) + ((uint32_t)(lc ^ (r & 7)) << 4);
            cpasync16(sa  + sw, As + (size_t)(row0 + r) * DM + ksub + lc * 8);
            cpasync16(sbB + sw, Bh + (size_t)(col0 + r) * DM + ksub + lc * 8);
        }
    };

    // prologue
#pragma unroll
    for (int s = 0; s < STAGES - 1; s++) { load_stage(s, s); cp_commit(); }

    for (int ch = 0; ch < NCH; ch++) {
        cp_wait<STAGES - 2>();
        __syncthreads();

        const int s = ch % STAGES;
        const uint32_t sa  = sb + (uint32_t)s * 2 * STAGE_BYTES;
        const uint32_t sbB = sa + STAGE_BYTES;

#pragma unroll
        for (int k16 = 0; k16 < 4; k16++) {
            uint32_t afrag[4][4];
#pragma unroll
            for (int mi = 0; mi < 4; mi++) {
                int r   = wm * 64 + mi * 16 + (lane & 15);
                int c16 = k16 * 2 + (lane >> 4);
                ldsm4(afrag[mi], sa + (uint32_t)(r * 128) + ((uint32_t)(c16 ^ (r & 7)) << 4));
            }
            uint32_t bfrag[2][4];
#pragma unroll
            for (int nb = 0; nb < 2; nb++) {
                int r   = wn * 32 + nb * 16 + (lane & 7) + ((lane & 16) ? 8 : 0);
                int c16 = k16 * 2 + ((lane >> 3) & 1);
                ldsm4(bfrag[nb], sbB + (uint32_t)(r * 128) + ((uint32_t)(c16 ^ (r & 7)) << 4));
            }
#pragma unroll
            for (int mi = 0; mi < 4; mi++)
#pragma unroll
                for (int ni = 0; ni < 4; ni++)
                    mma16816(acc[mi][ni], afrag[mi], &bfrag[ni >> 1][(ni & 1) * 2]);
        }

        const int nc = ch + STAGES - 1;
        if (nc < NCH) load_stage(nc % STAGES, nc);
        cp_commit();   // commit every iter (possibly-empty group keeps wait accounting uniform)
    }

    // ---- epilogue: bias add + fp32 store ----
    const int m_base = row0 + wm * 64;
    const int n_base = col0 + wn * 32;
    const int qr = lane >> 2;
    const int qc = (lane & 3) * 2;
#pragma unroll
    for (int ni = 0; ni < 4; ni++) {
        int colg = n_base + ni * 8 + qc;
        float bx = bias[colg], by = bias[colg + 1];
#pragma unroll
        for (int mi = 0; mi < 4; mi++) {
            int rg = m_base + mi * 16 + qr;
            float2 v0 = make_float2(acc[mi][ni][0] + bx, acc[mi][ni][1] + by);
            float2 v1 = make_float2(acc[mi][ni][2] + bx, acc[mi][ni][3] + by);
            *(float2*)(C + (size_t)rg * DM + colg)       = v0;
            *(float2*)(C + (size_t)(rg + 8) * DM + colg) = v1;
        }
    }
}

// ---------------- head-mixing sparsemax attention ----------------
// One block per (a,b) token. Output written directly into the
// (B,H,A,hd)->(B,4096,1024) reshape layout with GEMM-row m2 = r*8+b,
// r = h*256 + a/16, col = (a%16)*64 + d, as fp16 hi/lo.
__global__ void __launch_bounds__(256) attn_kernel(
    const float* __restrict__ Q, const float* __restrict__ K, const float* __restrict__ V,
    __half* __restrict__ x2hi, __half* __restrict__ x2lo)
{
    __shared__ float Qs[1024];
    __shared__ float Ks[16 * 65];
    __shared__ float Vs[1024];
    __shared__ float Ps[256];

    const int m = blockIdx.x;
    const int a = m >> 3, b = m & 7;
    const int t = threadIdx.x;

    {
        float4 q4 = ((const float4*)(Q + (size_t)m * DM))[t];
        ((float4*)Qs)[t] = q4;
        float4 k4 = ((const float4*)(K + (size_t)m * DM))[t];
        int ci = t * 4;
        int krow = ci >> 6, kcol = ci & 63;
        Ks[krow * 65 + kcol]     = k4.x;
        Ks[krow * 65 + kcol + 1] = k4.y;
        Ks[krow * 65 + kcol + 2] = k4.z;
        Ks[krow * 65 + kcol + 3] = k4.w;
        float4 v4 = ((const float4*)(V + (size_t)m * DM))[t];
        ((float4*)Vs)[t] = v4;
    }
    __syncthreads();

    {
        int h = t >> 4, g = t & 15;
        float accv = 0.0f;
#pragma unroll
        for (int i = 0; i < 64; i++)
            accv = fmaf(Qs[h * 64 + i], Ks[g * 65 + i], accv);
        Ps[t] = accv * SCORE_SCALE;
    }
    __syncthreads();

    if (t < 16) {
        float z[16];
#pragma unroll
        for (int i = 0; i < 16; i++) z[i] = Ps[t * 16 + i] * inv_alpha();
#pragma unroll
        for (int k = 2; k <= 16; k <<= 1) {
#pragma unroll
            for (int j = k >> 1; j > 0; j >>= 1) {
#pragma unroll
                for (int i = 0; i < 16; i++) {
                    int l = i ^ j;
                    if (l > i) {
                        bool up = ((i & k) == 0);
                        float zi = z[i], zl = z[l];
                        bool sw = up ? (zi > zl) : (zi < zl);
                        if (sw) { z[i] = zl; z[l] = zi; }
                    }
                }
            }
        }
        float cum = 0.0f, csel = 0.0f;
        int kc = 1;
#pragma unroll
        for (int r = 1; r <= 16; r++) {
            float v = z[16 - r];
            cum += v;
            if (v * (float)r > cum - 1.0f) { kc = r; csel = cum; }
        }
        float tau = (csel - 1.0f) / (float)kc;
#pragma unroll
        for (int i = 0; i < 16; i++) {
            float p = Ps[t * 16 + i] * inv_alpha() - tau;
            Ps[t * 16 + i] = p > 0.0f ? p : 0.0f;
        }
    }
    __syncthreads();

    {
        int h = t >> 4;
        int db = (t & 15) * 4;
        float o0 = 0, o1 = 0, o2 = 0, o3 = 0;
#pragma unroll
        for (int g = 0; g < 16; g++) {
            float p = Ps[h * 16 + g];
            const float* vr = Vs + g * 64 + db;
            o0 = fmaf(p, vr[0], o0);
            o1 = fmaf(p, vr[1], o1);
            o2 = fmaf(p, vr[2], o2);
            o3 = fmaf(p, vr[3], o3);
        }
        size_t m2  = ((size_t)(h * 256 + (a >> 4))) * 8 + (size_t)b;
        int    col = (a & 15) * 64 + db;
        size_t idx = m2 * DM + col;
        float o[4] = {o0, o1, o2, o3};
#pragma unroll
        for (int j = 0; j < 4; j++) {
            __half h16 = __float2half_rn(o[j]);
            x2hi[idx + j] = h16;
            x2lo[idx + j] = __float2half_rn(o[j] - __half2float(h16));
        }
    }
}

// ---------------- launcher ----------------
extern "C" void kernel_launch(void* const* d_in, const int* in_sizes, int n_in,
                              void* d_out, int out_size)
{
    (void)in_sizes; (void)n_in; (void)out_size;

    void *pahi, *palo, *pwh, *pq, *pk, *pv, *px2h, *px2l;
    cudaGetSymbolAddress(&pahi, g_ahi);
    cudaGetSymbolAddress(&palo, g_alo);
    cudaGetSymbolAddress(&pwh,  g_wh);
    cudaGetSymbolAddress(&pq,   g_q);
    cudaGetSymbolAddress(&pk,   g_k);
    cudaGetSymbolAddress(&pv,   g_v);
    cudaGetSymbolAddress(&px2h, g_x2hi);
    cudaGetSymbolAddress(&px2l, g_x2lo);

    __half* ahi  = (__half*)pahi;
    __half* alo  = (__half*)palo;
    __half* wh   = (__half*)pwh;
    float* qbuf  = (float*)pq;
    float* kbuf  = (float*)pk;
    float* vbuf  = (float*)pv;
    __half* x2hi = (__half*)px2h;
    __half* x2lo = (__half*)px2l;

    cudaFuncSetAttribute(gemm_hmma, cudaFuncAttributeMaxDynamicSharedMemorySize, GEMM_SMEM);

    // 1) split activations (query/key/value) into fp16 hi/lo
    const int actN8 = (int)(NELEM_ACT / 8);
    for (int i = 0; i < 3; i++) {
        split_fp16_kernel<<<actN8 / 256, 256>>>(
            (const float4*)d_in[i],
            (uint4*)(ahi + (size_t)i * NELEM_ACT),
            (uint4*)(alo + (size_t)i * NELEM_ACT), actN8);
    }
    // 2) convert weights (Wq,Wk,Wv,Wo at d_in 3,5,7,9) to fp16
    const int wN8 = (int)(NELEM_W / 8);
    const int wsrc[4] = {3, 5, 7, 9};
    for (int w = 0; w < 4; w++) {
        conv_fp16_kernel<<<wN8 / 256, 256>>>(
            (const float4*)d_in[wsrc[w]],
            (uint4*)(wh + (size_t)w * NELEM_W), wN8);
    }

    // 3) Q/K/V projections (fp32 out, bias added)
    dim3 ggrid(DM / BN, MROWS / BM);   // (8, 256)
    gemm_hmma<<<ggrid, 256, GEMM_SMEM>>>(
        ahi, alo, wh, (const float*)d_in[4], qbuf);
    gemm_hmma<<<ggrid, 256, GEMM_SMEM>>>(
        ahi + NELEM_ACT, alo + NELEM_ACT, wh + NELEM_W,
        (const float*)d_in[6], kbuf);
    gemm_hmma<<<ggrid, 256, GEMM_SMEM>>>(
        ahi + 2 * NELEM_ACT, alo + 2 * NELEM_ACT, wh + 2 * NELEM_W,
        (const float*)d_in[8], vbuf);

    // 4) sparsemax attention -> permuted X2 (hi/lo fp16)
    attn_kernel<<<MROWS, 256>>>(qbuf, kbuf, vbuf, x2hi, x2lo);

    // 5) output projection straight into d_out
    gemm_hmma<<<ggrid, 256, GEMM_SMEM>>>(
        x2hi, x2lo, wh + 3 * NELEM_W,
        (const float*)d_in[10], (float*)d_out);
}